// round 4
// baseline (speedup 1.0000x reference)
#include <cuda_runtime.h>
#include <math.h>

#define FDIM 128
#define GMAX 50000
#define CAP  192
#define OVF_MAX 4096

// ---------------- device scratch (zero-initialized .bss; self-restoring) ----------------
__device__ int g_cnt[GMAX];                 // per-segment node count (restored to 0 by pool)
__device__ int g_perm[(size_t)GMAX * CAP];  // bucketed node indices
__device__ int g_ovf[OVF_MAX];              // overflow node list (normally empty)
__device__ int g_novf;                      // overflow count (reset by pool's last block)
__device__ int g_is64;                      // seg dtype flag (written by scatter)
__device__ int g_done;                      // block-arrival ticket (reset by last block)

__device__ __forceinline__ float tanh_fast(float x) {
    float r;
    asm("tanh.approx.f32 %0, %1;" : "=f"(r) : "f"(x));
    return r;
}

__device__ __forceinline__ void facc(float4& a, const float4& v) {
    a.x += v.x; a.y += v.y; a.z += v.z; a.w += v.w;
}

// ---------------- kernel 1: scatter nodes into per-segment buckets ----------------
__global__ void __launch_bounds__(256) scatter_kernel(const void* __restrict__ seg, int N) {
    __shared__ int s_is64;
    if (threadIdx.x == 0) {
        // int64 ids < 2^32 have zero high words; 64 random int32 ids all-zero: p ~ 0
        const unsigned int* w = (const unsigned int*)seg;
        unsigned int acc = 0;
        #pragma unroll
        for (int k = 0; k < 64; k++) acc |= w[2 * k + 1];
        s_is64 = (acc == 0u) ? 1 : 0;
        if (blockIdx.x == 0) g_is64 = s_is64;
    }
    __syncthreads();
    const int is64 = s_is64;

    int base = (blockIdx.x * blockDim.x + threadIdx.x) * 4;
    if (base >= N) return;
    int cnt = min(4, N - base);

    int ids[4];
    if (cnt == 4) {
        if (is64) {
            const longlong2* p = (const longlong2*)((const long long*)seg + base);
            longlong2 v0 = __ldg(p), v1 = __ldg(p + 1);
            ids[0] = (int)v0.x; ids[1] = (int)v0.y; ids[2] = (int)v1.x; ids[3] = (int)v1.y;
        } else {
            int4 v = __ldg((const int4*)((const int*)seg + base));
            ids[0] = v.x; ids[1] = v.y; ids[2] = v.z; ids[3] = v.w;
        }
    } else {
        for (int j = 0; j < cnt; j++)
            ids[j] = is64 ? (int)((const long long*)seg)[base + j]
                          : ((const int*)seg)[base + j];
    }

    #pragma unroll
    for (int j = 0; j < 4; j++) {
        if (j >= cnt) break;
        int s = ids[j];
        int slot = atomicAdd(&g_cnt[s], 1);
        if (slot < CAP) {
            g_perm[(size_t)s * CAP + slot] = base + j;
        } else {
            int o = atomicAdd(&g_novf, 1);
            if (o < OVF_MAX) g_ovf[o] = base + j;
        }
    }
}

// ---------------- kernel 2: fused gather-pool + MLP ----------------
// Each warp owns 2 segments. The two gathers are INTERLEAVED in one loop so
// ~10 independent loads are in flight per iteration (latency hiding), then one
// W1 pass serves both GEMVs (2x L1 reuse). No __syncthreads in the hot path.
__global__ void __launch_bounds__(256) pool_mlp_kernel(
    const float* __restrict__ h,
    const void*  __restrict__ seg,
    const float* __restrict__ W1,   // [128,128] row-major: W1[k][c]
    const float* __restrict__ b1,   // [128]
    const float* __restrict__ W2,   // [128]
    const float* __restrict__ b2,   // [1]
    float* __restrict__ y, int G)
{
    __shared__ float sp[8][2][FDIM];            // 2 pooled rows per warp (8 KB)
    const int warp = threadIdx.x >> 5;
    const int lane = threadIdx.x & 31;
    const int gA = (blockIdx.x * 8 + warp) * 2;
    const int gB = gA + 1;
    const int nov = g_novf;                     // read before any block resets it
    const bool hasA = (gA < G);
    const bool hasB = (gB < G);

    int nA = 0, nB = 0;
    if (hasA) { nA = min(g_cnt[gA], CAP); if (lane == 0) g_cnt[gA] = 0; }
    if (hasB) { nB = min(g_cnt[gB], CAP); if (lane == 0) g_cnt[gB] = 0; }
    const int* pmA = &g_perm[(size_t)gA * CAP];
    const int* pmB = &g_perm[(size_t)gB * CAP];

    const float4 z4 = make_float4(0.f, 0.f, 0.f, 0.f);
    float4 aA0 = z4, aA1 = z4, aB0 = z4, aB1 = z4;

    const int maxn = max(nA, nB);
    #pragma unroll 2
    for (int i = 0; i < maxn; i += 4) {
        const bool dA = (i < nA);
        const bool dB = (i < nB);
        int4 ia, ib;
        if (dA) ia = __ldg((const int4*)(pmA + i));
        if (dB) ib = __ldg((const int4*)(pmB + i));

        float4 vA0 = z4, vA1 = z4, vA2 = z4, vA3 = z4;
        float4 vB0 = z4, vB1 = z4, vB2 = z4, vB3 = z4;
        if (dA) {
            vA0 = __ldcs((const float4*)(h + (size_t)ia.x * FDIM) + lane);
            if (i + 1 < nA) vA1 = __ldcs((const float4*)(h + (size_t)ia.y * FDIM) + lane);
            if (i + 2 < nA) vA2 = __ldcs((const float4*)(h + (size_t)ia.z * FDIM) + lane);
            if (i + 3 < nA) vA3 = __ldcs((const float4*)(h + (size_t)ia.w * FDIM) + lane);
        }
        if (dB) {
            vB0 = __ldcs((const float4*)(h + (size_t)ib.x * FDIM) + lane);
            if (i + 1 < nB) vB1 = __ldcs((const float4*)(h + (size_t)ib.y * FDIM) + lane);
            if (i + 2 < nB) vB2 = __ldcs((const float4*)(h + (size_t)ib.z * FDIM) + lane);
            if (i + 3 < nB) vB3 = __ldcs((const float4*)(h + (size_t)ib.w * FDIM) + lane);
        }
        facc(aA0, vA0); facc(aA1, vA1); facc(aA0, vA2); facc(aA1, vA3);
        facc(aB0, vB0); facc(aB1, vB1); facc(aB0, vB2); facc(aB1, vB3);
    }

    // overflow path (correctness safety net; empty for real data)
    if (nov > 0) {
        const int m = min(nov, OVF_MAX);
        const int is64 = g_is64;
        for (int k = 0; k < m; k++) {
            int nd = g_ovf[k];
            int s = is64 ? (int)((const long long*)seg)[nd]
                         : ((const int*)seg)[nd];
            if (s == gA || s == gB) {
                float4 v = __ldcs((const float4*)(h + (size_t)nd * FDIM) + lane);
                if (s == gA) facc(aA0, v); else facc(aB0, v);
            }
        }
    }

    float4 accA, accB;
    accA.x = aA0.x + aA1.x; accA.y = aA0.y + aA1.y;
    accA.z = aA0.z + aA1.z; accA.w = aA0.w + aA1.w;
    accB.x = aB0.x + aB1.x; accB.y = aB0.y + aB1.y;
    accB.z = aB0.z + aB1.z; accB.w = aB0.w + aB1.w;
    ((float4*)sp[warp][0])[lane] = accA;
    ((float4*)sp[warp][1])[lane] = accB;
    __syncwarp();

    if (hasA) {
        float4 bb = __ldg((const float4*)b1 + lane);
        float hA0 = bb.x, hA1 = bb.y, hA2 = bb.z, hA3 = bb.w;
        float hB0 = bb.x, hB1 = bb.y, hB2 = bb.z, hB3 = bb.w;
        const float4* W1v = (const float4*)W1;          // row k, chunk lane
        const float* sA = sp[warp][0];
        const float* sB = sp[warp][1];

        #pragma unroll 4
        for (int k = 0; k < FDIM; k++) {
            float4 w = __ldg(W1v + k * 32 + lane);      // one load, two uses
            float pA = sA[k];
            float pB = sB[k];
            hA0 = fmaf(pA, w.x, hA0); hB0 = fmaf(pB, w.x, hB0);
            hA1 = fmaf(pA, w.y, hA1); hB1 = fmaf(pB, w.y, hB1);
            hA2 = fmaf(pA, w.z, hA2); hB2 = fmaf(pB, w.z, hB2);
            hA3 = fmaf(pA, w.w, hA3); hB3 = fmaf(pB, w.w, hB3);
        }

        float4 w2 = __ldg((const float4*)W2 + lane);
        float pA = tanh_fast(hA0) * w2.x + tanh_fast(hA1) * w2.y
                 + tanh_fast(hA2) * w2.z + tanh_fast(hA3) * w2.w;
        float pB = tanh_fast(hB0) * w2.x + tanh_fast(hB1) * w2.y
                 + tanh_fast(hB2) * w2.z + tanh_fast(hB3) * w2.w;

        #pragma unroll
        for (int off = 16; off; off >>= 1) {
            pA += __shfl_down_sync(0xffffffffu, pA, off);
            pB += __shfl_down_sync(0xffffffffu, pB, off);
        }
        if (lane == 0) {
            float bias = __ldg(b2);
            y[gA] = pA + bias;
            if (hasB) y[gB] = pB + bias;
        }
    }

    // ---- elected last block resets overflow state for the next replay ----
    if (threadIdx.x == 0) {
        __threadfence();
        int t = atomicAdd(&g_done, 1);
        if (t == (int)gridDim.x - 1) {
            g_novf = 0;
            g_done = 0;
        }
    }
}

// ---------------- launch ----------------
extern "C" void kernel_launch(void* const* d_in, const int* in_sizes, int n_in,
                              void* d_out, int out_size) {
    const float* h   = (const float*)d_in[0];
    const void*  seg = d_in[1];
    const int N = in_sizes[0] / FDIM;
    const int G = out_size;          // OUT = 1

    int iw = -1;
    for (int i = 2; i < n_in; i++) {
        if (in_sizes[i] == FDIM * FDIM) { iw = i; break; }
    }
    const float* W1 = (const float*)d_in[iw];
    const float* b1 = (const float*)d_in[iw + 1];
    const float* W2 = (const float*)d_in[iw + 2];
    const float* b2 = (const float*)d_in[iw + 3];
    float* y = (float*)d_out;

    const int nodes_per_blk = 256 * 4;
    scatter_kernel<<<(N + nodes_per_blk - 1) / nodes_per_blk, 256>>>(seg, N);
    const int segs_per_blk = 16;     // 8 warps x 2 segments (interleaved)
    pool_mlp_kernel<<<(G + segs_per_blk - 1) / segs_per_blk, 256>>>(h, seg, W1, b1, W2, b2, y, G);
}

// round 5
// speedup vs baseline: 1.1737x; 1.1737x over previous
#include <cuda_runtime.h>
#include <math.h>

#define FDIM 128
#define GMAX 50000
#define CAP  192
#define OVF_MAX 4096

// ---------------- device scratch (zero-initialized .bss; self-restoring) ----------------
__device__ int g_cnt[GMAX];                 // per-segment node count (restored to 0 by pool)
__device__ int g_perm[(size_t)GMAX * CAP];  // bucketed node indices
__device__ int g_ovf[OVF_MAX];              // overflow node list (normally empty)
__device__ int g_novf;                      // overflow count (reset by pool's last block)
__device__ int g_is64;                      // seg dtype flag (written by scatter)
__device__ int g_done;                      // block-arrival ticket (reset by last block)

__device__ __forceinline__ float tanh_fast(float x) {
    float r;
    asm("tanh.approx.f32 %0, %1;" : "=f"(r) : "f"(x));
    return r;
}

__device__ __forceinline__ void facc(float4& a, const float4& v) {
    a.x += v.x; a.y += v.y; a.z += v.z; a.w += v.w;
}

// ---------------- kernel 1: scatter nodes into per-segment buckets ----------------
__global__ void __launch_bounds__(256) scatter_kernel(const void* __restrict__ seg, int N) {
    __shared__ int s_is64;
    if (threadIdx.x == 0) {
        // int64 ids < 2^32 have zero high words; 64 random int32 ids all-zero: p ~ 0
        const unsigned int* w = (const unsigned int*)seg;
        unsigned int acc = 0;
        #pragma unroll
        for (int k = 0; k < 64; k++) acc |= w[2 * k + 1];
        s_is64 = (acc == 0u) ? 1 : 0;
        if (blockIdx.x == 0) g_is64 = s_is64;
    }
    __syncthreads();
    const int is64 = s_is64;

    int base = (blockIdx.x * blockDim.x + threadIdx.x) * 4;
    if (base >= N) return;
    int cnt = min(4, N - base);

    int ids[4];
    if (cnt == 4) {
        if (is64) {
            const longlong2* p = (const longlong2*)((const long long*)seg + base);
            longlong2 v0 = __ldg(p), v1 = __ldg(p + 1);
            ids[0] = (int)v0.x; ids[1] = (int)v0.y; ids[2] = (int)v1.x; ids[3] = (int)v1.y;
        } else {
            int4 v = __ldg((const int4*)((const int*)seg + base));
            ids[0] = v.x; ids[1] = v.y; ids[2] = v.z; ids[3] = v.w;
        }
    } else {
        for (int j = 0; j < cnt; j++)
            ids[j] = is64 ? (int)((const long long*)seg)[base + j]
                          : ((const int*)seg)[base + j];
    }

    #pragma unroll
    for (int j = 0; j < 4; j++) {
        if (j >= cnt) break;
        int s = ids[j];
        int slot = atomicAdd(&g_cnt[s], 1);
        if (slot < CAP) {
            g_perm[(size_t)s * CAP + slot] = base + j;
        } else {
            int o = atomicAdd(&g_novf, 1);
            if (o < OVF_MAX) g_ovf[o] = base + j;
        }
    }
}

// ---------------- kernel 2: fused gather-pool + MLP ----------------
// ONE segment per warp, fully independent warps (the R1 structure that won).
// Slim register budget (<=42 via launch_bounds) -> 6 blocks/SM = 75% occupancy.
// Index prefetch (int2) breaks the idx->h serial chain at minimal reg cost.
__global__ void __launch_bounds__(256, 6) pool_mlp_kernel(
    const float* __restrict__ h,
    const void*  __restrict__ seg,
    const float* __restrict__ W1,   // [128,128] row-major: W1[k][c]
    const float* __restrict__ b1,   // [128]
    const float* __restrict__ W2,   // [128]
    const float* __restrict__ b2,   // [1]
    float* __restrict__ y, int G)
{
    __shared__ float sp[8][FDIM];               // pooled row per warp (4 KB)
    const int warp = threadIdx.x >> 5;
    const int lane = threadIdx.x & 31;
    const int g = blockIdx.x * 8 + warp;
    const int nov = g_novf;                     // read before any block resets it

    if (g < G) {
        const int n = g_cnt[g];
        if (lane == 0) g_cnt[g] = 0;            // self-restore for next replay
        const int nn = min(n, CAP);
        const int* pm = &g_perm[(size_t)g * CAP];

        float4 a0 = make_float4(0.f, 0.f, 0.f, 0.f);
        float4 a1 = a0;

        // software-pipelined gather: 2 nodes per iteration, next idx prefetched
        int2 id = (nn >= 2) ? __ldg((const int2*)pm) : make_int2(0, 0);
        int i = 0;
        for (; i + 2 <= nn; i += 2) {
            int2 nx = (i + 4 <= nn) ? __ldg((const int2*)(pm + i + 2)) : id;
            float4 v0 = __ldcs((const float4*)(h + (size_t)id.x * FDIM) + lane);
            float4 v1 = __ldcs((const float4*)(h + (size_t)id.y * FDIM) + lane);
            facc(a0, v0);
            facc(a1, v1);
            id = nx;
        }
        if (i < nn) {
            int nd = __ldg(pm + i);
            float4 v = __ldcs((const float4*)(h + (size_t)nd * FDIM) + lane);
            facc(a0, v);
        }

        // overflow path (correctness safety net; empty for real data)
        if (nov > 0) {
            const int m = min(nov, OVF_MAX);
            const int is64 = g_is64;
            for (int k = 0; k < m; k++) {
                int nd = g_ovf[k];
                int s = is64 ? (int)((const long long*)seg)[nd]
                             : ((const int*)seg)[nd];
                if (s == g) {
                    float4 v = __ldcs((const float4*)(h + (size_t)nd * FDIM) + lane);
                    facc(a0, v);
                }
            }
        }

        float4 acc;
        acc.x = a0.x + a1.x; acc.y = a0.y + a1.y;
        acc.z = a0.z + a1.z; acc.w = a0.w + a1.w;
        ((float4*)sp[warp])[lane] = acc;
        __syncwarp();

        // hidden[4l..4l+3] = tanh(b1 + pooled @ W1); y = hidden . W2 + b2
        float4 bb = __ldg((const float4*)b1 + lane);
        float h0 = bb.x, h1 = bb.y, h2 = bb.z, h3 = bb.w;
        const float4* W1v = (const float4*)W1;  // row k, chunk lane
        const float* sA = sp[warp];

        #pragma unroll 4
        for (int k = 0; k < FDIM; k++) {
            float4 w = __ldg(W1v + k * 32 + lane);
            float pk = sA[k];
            h0 = fmaf(pk, w.x, h0);
            h1 = fmaf(pk, w.y, h1);
            h2 = fmaf(pk, w.z, h2);
            h3 = fmaf(pk, w.w, h3);
        }

        float4 w2 = __ldg((const float4*)W2 + lane);
        float p = tanh_fast(h0) * w2.x + tanh_fast(h1) * w2.y
                + tanh_fast(h2) * w2.z + tanh_fast(h3) * w2.w;

        #pragma unroll
        for (int off = 16; off; off >>= 1)
            p += __shfl_down_sync(0xffffffffu, p, off);
        if (lane == 0) y[g] = p + __ldg(b2);
    }

    // ---- elected last block resets overflow state for the next replay ----
    if (threadIdx.x == 0) {
        __threadfence();
        int t = atomicAdd(&g_done, 1);
        if (t == (int)gridDim.x - 1) {
            g_novf = 0;
            g_done = 0;
        }
    }
}

// ---------------- launch ----------------
extern "C" void kernel_launch(void* const* d_in, const int* in_sizes, int n_in,
                              void* d_out, int out_size) {
    const float* h   = (const float*)d_in[0];
    const void*  seg = d_in[1];
    const int N = in_sizes[0] / FDIM;
    const int G = out_size;          // OUT = 1

    int iw = -1;
    for (int i = 2; i < n_in; i++) {
        if (in_sizes[i] == FDIM * FDIM) { iw = i; break; }
    }
    const float* W1 = (const float*)d_in[iw];
    const float* b1 = (const float*)d_in[iw + 1];
    const float* W2 = (const float*)d_in[iw + 2];
    const float* b2 = (const float*)d_in[iw + 3];
    float* y = (float*)d_out;

    const int nodes_per_blk = 256 * 4;
    scatter_kernel<<<(N + nodes_per_blk - 1) / nodes_per_blk, 256>>>(seg, N);
    pool_mlp_kernel<<<(G + 7) / 8, 256>>>(h, seg, W1, b1, W2, b2, y, G);
}

// round 6
// speedup vs baseline: 1.5375x; 1.3099x over previous
#include <cuda_runtime.h>
#include <math.h>

#define FDIM 128
#define GMAX 50000
#define CAP  192
#define OVF_MAX 4096

// ---------------- device scratch (zero-initialized .bss; self-restoring) ----------------
__device__ int g_cnt[GMAX];                 // per-segment node count (restored to 0 by pool)
__device__ int g_perm[(size_t)GMAX * CAP];  // bucketed node indices
__device__ int g_ovf[OVF_MAX];              // overflow node list (normally empty)
__device__ int g_novf;                      // overflow count (reset by pool's last block)
__device__ int g_is64;                      // seg dtype flag (written by scatter)
__device__ int g_done;                      // block-arrival ticket (reset by last block)

__device__ __forceinline__ float tanh_fast(float x) {
    float r;
    asm("tanh.approx.f32 %0, %1;" : "=f"(r) : "f"(x));
    return r;
}

__device__ __forceinline__ void facc(float4& a, const float4& v) {
    a.x += v.x; a.y += v.y; a.z += v.z; a.w += v.w;
}

// ---------------- kernel 1: scatter nodes into per-segment buckets ----------------
__global__ void __launch_bounds__(256) scatter_kernel(const void* __restrict__ seg, int N) {
    __shared__ int s_is64;
    if (threadIdx.x == 0) {
        // int64 ids < 2^32 have zero high words; 64 random int32 ids all-zero: p ~ 0
        const unsigned int* w = (const unsigned int*)seg;
        unsigned int acc = 0;
        #pragma unroll
        for (int k = 0; k < 64; k++) acc |= w[2 * k + 1];
        s_is64 = (acc == 0u) ? 1 : 0;
        if (blockIdx.x == 0) g_is64 = s_is64;
    }
    __syncthreads();
    const int is64 = s_is64;

    int base = (blockIdx.x * blockDim.x + threadIdx.x) * 4;
    if (base >= N) return;
    int cnt = min(4, N - base);

    int ids[4];
    if (cnt == 4) {
        if (is64) {
            const longlong2* p = (const longlong2*)((const long long*)seg + base);
            longlong2 v0 = __ldg(p), v1 = __ldg(p + 1);
            ids[0] = (int)v0.x; ids[1] = (int)v0.y; ids[2] = (int)v1.x; ids[3] = (int)v1.y;
        } else {
            int4 v = __ldg((const int4*)((const int*)seg + base));
            ids[0] = v.x; ids[1] = v.y; ids[2] = v.z; ids[3] = v.w;
        }
    } else {
        for (int j = 0; j < cnt; j++)
            ids[j] = is64 ? (int)((const long long*)seg)[base + j]
                          : ((const int*)seg)[base + j];
    }

    #pragma unroll
    for (int j = 0; j < 4; j++) {
        if (j >= cnt) break;
        int s = ids[j];
        int slot = atomicAdd(&g_cnt[s], 1);
        if (slot < CAP) {
            g_perm[(size_t)s * CAP + slot] = base + j;
        } else {
            int o = atomicAdd(&g_novf, 1);
            if (o < OVF_MAX) g_ovf[o] = base + j;
        }
    }
}

// ---------------- kernel 2: fused gather-pool + MLP ----------------
// One segment per warp, independent warps. 128-thread blocks for fine register
// packing (~40 warps/SM). Gather: 4 rows per iteration with the NEXT int4 index
// prefetched, so consecutive iterations' row loads overlap (~8 rows in flight).
__global__ void __launch_bounds__(128) pool_mlp_kernel(
    const float* __restrict__ h,
    const void*  __restrict__ seg,
    const float* __restrict__ W1,   // [128,128] row-major: W1[k][c]
    const float* __restrict__ b1,   // [128]
    const float* __restrict__ W2,   // [128]
    const float* __restrict__ b2,   // [1]
    float* __restrict__ y, int G)
{
    __shared__ float sp[4][FDIM];               // pooled row per warp (2 KB)
    const int warp = threadIdx.x >> 5;
    const int lane = threadIdx.x & 31;
    const int g = blockIdx.x * 4 + warp;
    const int nov = g_novf;                     // read before any block resets it

    if (g < G) {
        const int n = g_cnt[g];
        if (lane == 0) g_cnt[g] = 0;            // self-restore for next replay
        const int nn = min(n, CAP);
        const int* pm = &g_perm[(size_t)g * CAP];

        float4 a0 = make_float4(0.f, 0.f, 0.f, 0.f);
        float4 a1 = a0, a2 = a0, a3 = a0;

        // 4-row batches, index vector prefetched one iteration ahead
        int4 id = make_int4(0, 0, 0, 0);
        if (nn >= 4) id = __ldg((const int4*)pm);
        int i = 0;
        for (; i + 4 <= nn; i += 4) {
            int4 nx = id;
            if (i + 8 <= nn) nx = __ldg((const int4*)(pm + i + 4));
            float4 v0 = __ldcs((const float4*)(h + (size_t)id.x * FDIM) + lane);
            float4 v1 = __ldcs((const float4*)(h + (size_t)id.y * FDIM) + lane);
            float4 v2 = __ldcs((const float4*)(h + (size_t)id.z * FDIM) + lane);
            float4 v3 = __ldcs((const float4*)(h + (size_t)id.w * FDIM) + lane);
            facc(a0, v0); facc(a1, v1); facc(a2, v2); facc(a3, v3);
            id = nx;
        }
        for (; i < nn; i++) {
            int nd = __ldg(pm + i);
            float4 v = __ldcs((const float4*)(h + (size_t)nd * FDIM) + lane);
            facc(a0, v);
        }

        // overflow path (correctness safety net; empty for real data)
        if (nov > 0) {
            const int m = min(nov, OVF_MAX);
            const int is64 = g_is64;
            for (int k = 0; k < m; k++) {
                int nd = g_ovf[k];
                int s = is64 ? (int)((const long long*)seg)[nd]
                             : ((const int*)seg)[nd];
                if (s == g) {
                    float4 v = __ldcs((const float4*)(h + (size_t)nd * FDIM) + lane);
                    facc(a0, v);
                }
            }
        }

        float4 acc;
        acc.x = (a0.x + a1.x) + (a2.x + a3.x);
        acc.y = (a0.y + a1.y) + (a2.y + a3.y);
        acc.z = (a0.z + a1.z) + (a2.z + a3.z);
        acc.w = (a0.w + a1.w) + (a2.w + a3.w);
        ((float4*)sp[warp])[lane] = acc;
        __syncwarp();

        // hidden[4l..4l+3] = tanh(b1 + pooled @ W1); y = hidden . W2 + b2
        float4 bb = __ldg((const float4*)b1 + lane);
        float h0 = bb.x, h1 = bb.y, h2 = bb.z, h3 = bb.w;
        const float4* W1v = (const float4*)W1;  // row k, chunk lane
        const float* sA = sp[warp];

        #pragma unroll 4
        for (int k = 0; k < FDIM; k++) {
            float4 w = __ldg(W1v + k * 32 + lane);
            float pk = sA[k];
            h0 = fmaf(pk, w.x, h0);
            h1 = fmaf(pk, w.y, h1);
            h2 = fmaf(pk, w.z, h2);
            h3 = fmaf(pk, w.w, h3);
        }

        float4 w2 = __ldg((const float4*)W2 + lane);
        float p = tanh_fast(h0) * w2.x + tanh_fast(h1) * w2.y
                + tanh_fast(h2) * w2.z + tanh_fast(h3) * w2.w;

        #pragma unroll
        for (int off = 16; off; off >>= 1)
            p += __shfl_down_sync(0xffffffffu, p, off);
        if (lane == 0) y[g] = p + __ldg(b2);
    }

    // ---- elected last block resets overflow state for the next replay ----
    if (threadIdx.x == 0) {
        __threadfence();
        int t = atomicAdd(&g_done, 1);
        if (t == (int)gridDim.x - 1) {
            g_novf = 0;
            g_done = 0;
        }
    }
}

// ---------------- launch ----------------
extern "C" void kernel_launch(void* const* d_in, const int* in_sizes, int n_in,
                              void* d_out, int out_size) {
    const float* h   = (const float*)d_in[0];
    const void*  seg = d_in[1];
    const int N = in_sizes[0] / FDIM;
    const int G = out_size;          // OUT = 1

    int iw = -1;
    for (int i = 2; i < n_in; i++) {
        if (in_sizes[i] == FDIM * FDIM) { iw = i; break; }
    }
    const float* W1 = (const float*)d_in[iw];
    const float* b1 = (const float*)d_in[iw + 1];
    const float* W2 = (const float*)d_in[iw + 2];
    const float* b2 = (const float*)d_in[iw + 3];
    float* y = (float*)d_out;

    const int nodes_per_blk = 256 * 4;
    scatter_kernel<<<(N + nodes_per_blk - 1) / nodes_per_blk, 256>>>(seg, N);
    pool_mlp_kernel<<<(G + 3) / 4, 128>>>(h, seg, W1, b1, W2, b2, y, G);
}